// round 3
// baseline (speedup 1.0000x reference)
#include <cuda_runtime.h>
#include <cuda_bf16.h>

// Problem constants
#define NN   64
#define LL   1024
#define DD   512
#define LI_  1022
#define SS   127
#define OUTC 300
#define EPSF 1e-5f

// Scratch for span means (allocation-free rule: __device__ global)
__device__ float g_means[(size_t)NN * SS * DD];

// packed fp32x2 FMA (Blackwell FFMA2 — PTX only)
#define FMA_F32X2(d, a, b, c) \
    asm("fma.rn.f32x2 %0, %1, %2, %3;" : "=l"(d) : "l"(a), "l"(b), "l"(c))
#define PACK_DUP_F32X2(d, s) \
    asm("mov.b64 %0, {%1, %1};" : "=l"(d) : "r"(__float_as_uint(s)))
#define UNPACK_F32X2(lo, hi, v) \
    asm("mov.b64 {%0, %1}, %2;" : "=f"(lo), "=f"(hi) : "l"(v))

__device__ __forceinline__ unsigned smem_u32(const void* p) {
    return (unsigned)__cvta_generic_to_shared(p);
}
__device__ __forceinline__ void cp_async4(unsigned dst, const void* src) {
    asm volatile("cp.async.ca.shared.global [%0], [%1], 4;" :: "r"(dst), "l"(src));
}
__device__ __forceinline__ void cp_commit() {
    asm volatile("cp.async.commit_group;");
}
template <int N>
__device__ __forceinline__ void cp_wait() {
    asm volatile("cp.async.wait_group %0;" :: "n"(N));
}

// ---------------------------------------------------------------------------
// Kernel 1: span means + copy of `use = t1[:,0,:]`
// ---------------------------------------------------------------------------
__global__ void means_kernel(const float* __restrict__ t1,
                             const int* __restrict__ ws32,
                             float* __restrict__ out_use)
{
    int b = blockIdx.x;            // 0 .. NN*SS-1
    int n = b / SS;
    int s = b - n * SS;

    // word_seq dtype detection (int32 vs int64 storage).
    bool is64 = (ws32[1] == 0 && ws32[3] == 0);
    long long start, end;
    if (is64) {
        const long long* ws64 = (const long long*)ws32;
        start = ws64[(size_t)(n * SS + s) * 2];
        end   = ws64[(size_t)(n * SS + s) * 2 + 1];
    } else {
        start = ws32[(size_t)(n * SS + s) * 2];
        end   = ws32[(size_t)(n * SS + s) * 2 + 1];
    }
    if (start > (long long)(LI_ - 1)) start = LI_ - 1;
    if (end   > (long long)LI_)       end   = LI_;
    int cnt = (int)(end - start);

    int d4 = threadIdx.x;          // 0..127 -> float4 slot
    const float4* base =
        (const float4*)(t1 + ((size_t)n * LL + 1 + (size_t)start) * DD) + d4;

    float4 acc = make_float4(0.f, 0.f, 0.f, 0.f);
    if (cnt == 8) {
        float4 v[8];
#pragma unroll
        for (int r = 0; r < 8; ++r) v[r] = base[(size_t)r * (DD / 4)];
#pragma unroll
        for (int r = 0; r < 8; ++r) {
            acc.x += v[r].x; acc.y += v[r].y; acc.z += v[r].z; acc.w += v[r].w;
        }
    } else {
        for (int r = 0; r < cnt; ++r) {
            float4 v = base[(size_t)r * (DD / 4)];
            acc.x += v.x; acc.y += v.y; acc.z += v.z; acc.w += v.w;
        }
    }
    float inv = 1.0f / (float)cnt;
    acc.x *= inv; acc.y *= inv; acc.z *= inv; acc.w *= inv;
    ((float4*)(g_means + (size_t)b * DD))[d4] = acc;

    if (s == 0) {
        ((float4*)(out_use + (size_t)n * DD))[d4] =
            ((const float4*)(t1 + (size_t)n * LL * DD))[d4];
    }
}

// ---------------------------------------------------------------------------
// Kernel 2: GEMM h = means @ W^T + b, fused LayerNorm over OUT=300.
// 256 threads, BM=64 rows x 300 cols, BK=16, cp.async double-buffered.
// Thread micro-tile: 4 row-PAIRS x 10 cols via fma.rn.f32x2.
// smem: sA[2][16][64] (k-major, rows contiguous), sB[2][16][320] (k-major,
// cols contiguous -> conflict-free LDS), exactly 48KB.
// ---------------------------------------------------------------------------
#define BM 64
#define BK 16
#define NTILES (DD / BK)   // 32

__global__ __launch_bounds__(256, 1)
void gemm_ln_kernel(const float* __restrict__ W,      // [300,512] row-major
                    const float* __restrict__ blin,   // [300]
                    const float* __restrict__ gamma,  // [300]
                    const float* __restrict__ beta,   // [300]
                    float* __restrict__ out)          // [8128,300]
{
    __shared__ float sA[2][BK][64];    // 8 KB
    __shared__ float sB[2][BK][320];   // 40 KB

    int t    = threadIdx.x;
    int w    = t >> 5;     // warp 0..7
    int lane = t & 31;
    int rowBase = blockIdx.x * BM;

    const float* Ablk = g_means + (size_t)rowBase * DD;

    // Zero-fill sB cols [300,320) once (both buffers, all k): 2*16*20=640 slots
    for (int i = t; i < 2 * BK * 20; i += 256) {
        int buf = i / (BK * 20);
        int rem = i - buf * (BK * 20);
        int k = rem / 20;
        int c = 300 + rem % 20;
        sB[buf][k][c] = 0.f;
    }
    __syncthreads();

    // staging maps (per tile):
    //  A: 64x16 = 1024 elems, 4 per thread:  lin = t+256*i, r=lin>>4, k=lin&15
    //  B: 300x16 = 4800 elems, <=19/thread:  lin = t+256*i, c=lin>>4, k=lin&15
    auto issue_tile = [&](int tile, int buf) {
        int kc = tile * BK;
#pragma unroll
        for (int i = 0; i < 4; i++) {
            int lin = t + 256 * i;
            int r = lin >> 4, k = lin & 15;
            cp_async4(smem_u32(&sA[buf][k][r]), Ablk + (size_t)r * DD + kc + k);
        }
#pragma unroll
        for (int i = 0; i < 19; i++) {
            int lin = t + 256 * i;
            int c = lin >> 4, k = lin & 15;
            if (c < OUTC)
                cp_async4(smem_u32(&sB[buf][k][c]), W + (size_t)c * DD + kc + k);
        }
        cp_commit();
    };

    unsigned long long acc2[4][10];
#pragma unroll
    for (int i = 0; i < 4; i++)
#pragma unroll
        for (int j = 0; j < 10; j++) acc2[i][j] = 0ull;

    issue_tile(0, 0);

    for (int tile = 0; tile < NTILES; ++tile) {
        int buf = tile & 1;
        if (tile + 1 < NTILES) {
            issue_tile(tile + 1, buf ^ 1);
            cp_wait<1>();
        } else {
            cp_wait<0>();
        }
        __syncthreads();

#pragma unroll
        for (int k = 0; k < BK; k++) {
            unsigned long long a2[4], b2[10];
#pragma unroll
            for (int i = 0; i < 4; i++)   // LDS.64 broadcast, rows 2i,2i+1
                a2[i] = *reinterpret_cast<const unsigned long long*>(
                            &sA[buf][k][w * 8 + 2 * i]);
#pragma unroll
            for (int j = 0; j < 10; j++) {
                float b = sB[buf][k][lane + 32 * j];   // conflict-free
                PACK_DUP_F32X2(b2[j], b);
            }
#pragma unroll
            for (int i = 0; i < 4; i++)
#pragma unroll
                for (int j = 0; j < 10; j++)
                    FMA_F32X2(acc2[i][j], a2[i], b2[j], acc2[i][j]);
        }
        __syncthreads();   // done reading buf before tile+2 overwrites it
    }

    // epilogue: bias + per-row LayerNorm (warp-level; pair = rows 2i, 2i+1)
#pragma unroll
    for (int i = 0; i < 4; i++) {
        float vL[10], vH[10];
        float sumL = 0.f, sqL = 0.f, sumH = 0.f, sqH = 0.f;
#pragma unroll
        for (int j = 0; j < 10; j++) {
            int c = lane + 32 * j;
            float lo, hi;
            UNPACK_F32X2(lo, hi, acc2[i][j]);
            if (c < OUTC) {
                float bb = blin[c];
                lo += bb; hi += bb;
                vL[j] = lo; vH[j] = hi;
                sumL += lo; sqL += lo * lo;
                sumH += hi; sqH += hi * hi;
            }
        }
#pragma unroll
        for (int off = 16; off; off >>= 1) {
            sumL += __shfl_xor_sync(0xffffffffu, sumL, off);
            sqL  += __shfl_xor_sync(0xffffffffu, sqL,  off);
            sumH += __shfl_xor_sync(0xffffffffu, sumH, off);
            sqH  += __shfl_xor_sync(0xffffffffu, sqH,  off);
        }
        float muL  = sumL * (1.0f / OUTC);
        float invL = rsqrtf(sqL * (1.0f / OUTC) - muL * muL + EPSF);
        float muH  = sumH * (1.0f / OUTC);
        float invH = rsqrtf(sqH * (1.0f / OUTC) - muH * muH + EPSF);

        int rowL = rowBase + w * 8 + 2 * i;
        float* oL = out + (size_t)rowL * OUTC;
        float* oH = oL + OUTC;
#pragma unroll
        for (int j = 0; j < 10; j++) {
            int c = lane + 32 * j;
            if (c < OUTC) {
                float g = gamma[c], be = beta[c];
                oL[c] = (vL[j] - muL) * invL * g + be;
                oH[c] = (vH[j] - muH) * invH * g + be;
            }
        }
    }
}

// ---------------------------------------------------------------------------
// Inputs (metadata order): t1, word_seq, key_padding_mask, w_lin, b_lin,
// gamma, beta.  Output: tuple (out[64,127,300], use[64,512]) concatenated.
// ---------------------------------------------------------------------------
extern "C" void kernel_launch(void* const* d_in, const int* in_sizes, int n_in,
                              void* d_out, int out_size)
{
    const float* t1    = (const float*)d_in[0];
    const int*   ws    = (const int*)  d_in[1];
    const float* W     = (const float*)d_in[3];
    const float* blin  = (const float*)d_in[4];
    const float* gamma = (const float*)d_in[5];
    const float* beta  = (const float*)d_in[6];

    float* out = (float*)d_out;
    float* use = out + (size_t)NN * SS * OUTC;

    means_kernel<<<NN * SS, 128>>>(t1, ws, use);
    gemm_ln_kernel<<<SS, 256>>>(W, blin, gamma, beta, out);
}

// round 4
// speedup vs baseline: 1.3074x; 1.3074x over previous
#include <cuda_runtime.h>
#include <cuda_bf16.h>

// Problem constants
#define NN   64
#define LL   1024
#define DD   512
#define LI_  1022
#define SS   127
#define OUTC 300
#define EPSF 1e-5f

// Scratch for span means (allocation-free rule: __device__ global)
__device__ float g_means[(size_t)NN * SS * DD];

// packed fp32x2 FMA (Blackwell FFMA2 — PTX only)
#define FMA_F32X2(d, a, b, c) \
    asm("fma.rn.f32x2 %0, %1, %2, %3;" : "=l"(d) : "l"(a), "l"(b), "l"(c))
#define UNPACK_F32X2(lo, hi, v) \
    asm("mov.b64 {%0, %1}, %2;" : "=f"(lo), "=f"(hi) : "l"(v))

// ---------------------------------------------------------------------------
// Kernel 1: span means + copy of `use = t1[:,0,:]`
// ---------------------------------------------------------------------------
__global__ void means_kernel(const float* __restrict__ t1,
                             const int* __restrict__ ws32,
                             float* __restrict__ out_use)
{
    int b = blockIdx.x;            // 0 .. NN*SS-1
    int n = b / SS;
    int s = b - n * SS;

    // word_seq dtype detection (int32 vs int64 storage).
    bool is64 = (ws32[1] == 0 && ws32[3] == 0);
    long long start, end;
    if (is64) {
        const long long* ws64 = (const long long*)ws32;
        start = ws64[(size_t)(n * SS + s) * 2];
        end   = ws64[(size_t)(n * SS + s) * 2 + 1];
    } else {
        start = ws32[(size_t)(n * SS + s) * 2];
        end   = ws32[(size_t)(n * SS + s) * 2 + 1];
    }
    if (start > (long long)(LI_ - 1)) start = LI_ - 1;
    if (end   > (long long)LI_)       end   = LI_;
    int cnt = (int)(end - start);

    int d4 = threadIdx.x;          // 0..127 -> float4 slot
    const float4* base =
        (const float4*)(t1 + ((size_t)n * LL + 1 + (size_t)start) * DD) + d4;

    float4 acc = make_float4(0.f, 0.f, 0.f, 0.f);
    if (cnt == 8) {
        float4 v[8];
#pragma unroll
        for (int r = 0; r < 8; ++r) v[r] = base[(size_t)r * (DD / 4)];
#pragma unroll
        for (int r = 0; r < 8; ++r) {
            acc.x += v[r].x; acc.y += v[r].y; acc.z += v[r].z; acc.w += v[r].w;
        }
    } else {
        for (int r = 0; r < cnt; ++r) {
            float4 v = base[(size_t)r * (DD / 4)];
            acc.x += v.x; acc.y += v.y; acc.z += v.z; acc.w += v.w;
        }
    }
    float inv = 1.0f / (float)cnt;
    acc.x *= inv; acc.y *= inv; acc.z *= inv; acc.w *= inv;
    ((float4*)(g_means + (size_t)b * DD))[d4] = acc;

    if (s == 0) {
        ((float4*)(out_use + (size_t)n * DD))[d4] =
            ((const float4*)(t1 + (size_t)n * LL * DD))[d4];
    }
}

// ---------------------------------------------------------------------------
// Kernel 2: GEMM h = means @ W^T + b, fused LayerNorm over OUT=300.
// 512 threads (16 warps -> 4 warps/SMSP), BM=64, BK=16, reg double-buffer.
// Warp w owns rows 4w..4w+3; thread micro-tile = 4 rows x 5 col-PAIRS.
// sA2[k][r] holds A duplicated {v,v} -> LDS.64, no packing.
// sB[k][c] column-contiguous -> float2 LDS.64 for col pairs.
// ---------------------------------------------------------------------------
#define BM 64
#define BK 16
#define NTILES (DD / BK)    // 32
#define SB_STRIDE 322       // even (8B-aligned f2) + conflict-free STS
#define SA_STRIDE 65        // conflict-free duplicated STS

__global__ __launch_bounds__(512, 1)
void gemm_ln_kernel(const float* __restrict__ W,      // [300,512] row-major
                    const float* __restrict__ blin,   // [300]
                    const float* __restrict__ gamma,  // [300]
                    const float* __restrict__ beta,   // [300]
                    float* __restrict__ out)          // [8128,300]
{
    __shared__ float2 sA2[2][BK][SA_STRIDE];   // ~16.6 KB
    __shared__ float  sB [2][BK][SB_STRIDE];   // ~41.2 KB

    int t    = threadIdx.x;
    int w    = t >> 5;       // warp 0..15
    int lane = t & 31;
    int rowBase = blockIdx.x * BM;

    const float* Ablk = g_means + (size_t)rowBase * DD;

    // zero-fill sB padding cols [300,322) once, both buffers
    for (int i = t; i < 2 * BK * (SB_STRIDE - OUTC); i += 512) {
        int buf = i / (BK * (SB_STRIDE - OUTC));
        int rem = i - buf * (BK * (SB_STRIDE - OUTC));
        int k = rem / (SB_STRIDE - OUTC);
        int c = OUTC + rem % (SB_STRIDE - OUTC);
        sB[buf][k][c] = 0.f;
    }

    unsigned long long acc2[4][5];
#pragma unroll
    for (int i = 0; i < 4; i++)
#pragma unroll
        for (int j = 0; j < 5; j++) acc2[i][j] = 0ull;

    // staging decomposition (fixed per thread)
    int rA0 = t >> 4,        kA = t & 15;          // A: i=0 -> r=rA0, i=1 -> r=rA0+32
    // B: lin = t + 512*i ; c = lin>>4, k = lin&15
    float rgA[2];
    float rgB[10];

    // prologue: tile 0 -> regs -> smem buf0
    {
        int kc = 0;
        rgA[0] = Ablk[(size_t)rA0 * DD + kc + kA];
        rgA[1] = Ablk[(size_t)(rA0 + 32) * DD + kc + kA];
#pragma unroll
        for (int i = 0; i < 10; i++) {
            int lin = t + 512 * i;
            int c = lin >> 4, k = lin & 15;
            if (c < OUTC) rgB[i] = W[(size_t)c * DD + kc + k];
        }
        sA2[0][kA][rA0]      = make_float2(rgA[0], rgA[0]);
        sA2[0][kA][rA0 + 32] = make_float2(rgA[1], rgA[1]);
#pragma unroll
        for (int i = 0; i < 10; i++) {
            int lin = t + 512 * i;
            int c = lin >> 4, k = lin & 15;
            if (c < OUTC) sB[0][k][c] = rgB[i];
        }
    }
    __syncthreads();

    int colBase = 2 * lane;      // thread's first column

    for (int tile = 0; tile < NTILES; ++tile) {
        int buf = tile & 1;

        // issue next-tile LDGs early (latency hidden by compute)
        if (tile + 1 < NTILES) {
            int kc = (tile + 1) * BK;
            rgA[0] = Ablk[(size_t)rA0 * DD + kc + kA];
            rgA[1] = Ablk[(size_t)(rA0 + 32) * DD + kc + kA];
#pragma unroll
            for (int i = 0; i < 10; i++) {
                int lin = t + 512 * i;
                int c = lin >> 4, k = lin & 15;
                if (c < OUTC) rgB[i] = W[(size_t)c * DD + kc + k];
            }
        }

        // compute
#pragma unroll
        for (int k = 0; k < BK; k++) {
            unsigned long long a2[4], b2[5];
#pragma unroll
            for (int i = 0; i < 4; i++)
                a2[i] = *reinterpret_cast<const unsigned long long*>(
                            &sA2[buf][k][4 * w + i]);        // broadcast LDS.64
#pragma unroll
            for (int j = 0; j < 5; j++)
                b2[j] = *reinterpret_cast<const unsigned long long*>(
                            &sB[buf][k][colBase + 64 * j]);  // cf-free LDS.64
#pragma unroll
            for (int i = 0; i < 4; i++)
#pragma unroll
                for (int j = 0; j < 5; j++)
                    FMA_F32X2(acc2[i][j], a2[i], b2[j], acc2[i][j]);
        }

        // store next tile into the other buffer
        if (tile + 1 < NTILES) {
            int nb = buf ^ 1;
            sA2[nb][kA][rA0]      = make_float2(rgA[0], rgA[0]);
            sA2[nb][kA][rA0 + 32] = make_float2(rgA[1], rgA[1]);
#pragma unroll
            for (int i = 0; i < 10; i++) {
                int lin = t + 512 * i;
                int c = lin >> 4, k = lin & 15;
                if (c < OUTC) sB[nb][k][c] = rgB[i];
            }
        }
        __syncthreads();
    }

    // epilogue: bias + per-row LayerNorm; thread holds 4 rows x 5 col-pairs
    const float2* blin2  = (const float2*)blin;
    const float2* gamma2 = (const float2*)gamma;
    const float2* beta2  = (const float2*)beta;

#pragma unroll
    for (int i = 0; i < 4; i++) {
        float ve[5], vo[5];
        float sum = 0.f, sq = 0.f;
#pragma unroll
        for (int j = 0; j < 5; j++) {
            int c0 = colBase + 64 * j;           // even; pair = (c0, c0+1)
            float lo, hi;
            UNPACK_F32X2(lo, hi, acc2[i][j]);
            if (c0 < OUTC) {
                float2 bb = blin2[c0 >> 1];
                lo += bb.x; hi += bb.y;
                ve[j] = lo; vo[j] = hi;
                sum += lo + hi;
                sq  += lo * lo + hi * hi;
            }
        }
#pragma unroll
        for (int off = 16; off; off >>= 1) {
            sum += __shfl_xor_sync(0xffffffffu, sum, off);
            sq  += __shfl_xor_sync(0xffffffffu, sq,  off);
        }
        float mu  = sum * (1.0f / OUTC);
        float inv = rsqrtf(sq * (1.0f / OUTC) - mu * mu + EPSF);

        int row = rowBase + 4 * w + i;
        float* o = out + (size_t)row * OUTC;
#pragma unroll
        for (int j = 0; j < 5; j++) {
            int c0 = colBase + 64 * j;
            if (c0 < OUTC) {
                float2 g = gamma2[c0 >> 1];
                float2 be = beta2[c0 >> 1];
                float2 r;
                r.x = (ve[j] - mu) * inv * g.x + be.x;
                r.y = (vo[j] - mu) * inv * g.y + be.y;
                *reinterpret_cast<float2*>(&o[c0]) = r;
            }
        }
    }
}

// ---------------------------------------------------------------------------
// Inputs (metadata order): t1, word_seq, key_padding_mask, w_lin, b_lin,
// gamma, beta.  Output: tuple (out[64,127,300], use[64,512]) concatenated.
// ---------------------------------------------------------------------------
extern "C" void kernel_launch(void* const* d_in, const int* in_sizes, int n_in,
                              void* d_out, int out_size)
{
    const float* t1    = (const float*)d_in[0];
    const int*   ws    = (const int*)  d_in[1];
    const float* W     = (const float*)d_in[3];
    const float* blin  = (const float*)d_in[4];
    const float* gamma = (const float*)d_in[5];
    const float* beta  = (const float*)d_in[6];

    float* out = (float*)d_out;
    float* use = out + (size_t)NN * SS * OUTC;

    means_kernel<<<NN * SS, 128>>>(t1, ws, use);
    gemm_ln_kernel<<<SS, 512>>>(W, blin, gamma, beta, out);
}